// round 3
// baseline (speedup 1.0000x reference)
#include <cuda_runtime.h>

#define C      128
#define CH     64          // c/2; also number of i-pairs
#define KNB    16
#define PB     8           // points per warp
#define WARPS  8
#define THREADS 256
#define NPTS   (8*4096)

typedef unsigned long long u64;

// Weight matrices in i-pair-interleaved layout:
//   g_Bp [(I*C + j)*2 + t] = B[2I+t][j] * (0.125*log2e),  B[i][j] = sum_o wq[o][i]*wk[o][j]
//   g_wvp[(I*C + j)*2 + t] = wv[j][2I+t]                  (i.e. wvT[2I+t][j])
__device__ float g_Bp [C*C];
__device__ float g_wvp[C*C];

__global__ void precompute_kernel(const float* __restrict__ wq,
                                  const float* __restrict__ wk,
                                  const float* __restrict__ wv) {
    const int i = blockIdx.x;   // 0..127 (input channel)
    const int j = threadIdx.x;  // 0..127 (output channel)
    float acc = 0.f;
#pragma unroll
    for (int o = 0; o < CH; ++o)
        acc = fmaf(wq[o*C + i], wk[o*C + j], acc);
    const float lg2e8 = 0.125f * 1.4426950408889634f;   // fold softmax scale + log2(e)
    g_Bp [((i>>1)*C + j)*2 + (i&1)] = acc * lg2e8;
    g_wvp[((i>>1)*C + j)*2 + (i&1)] = wv[j*C + i];
}

// ---- packed fp32x2 helpers (Blackwell sm_100+) ----
__device__ __forceinline__ void ffma2(u64& d, u64 a, u64 b) {
    asm("fma.rn.f32x2 %0, %1, %2, %0;" : "+l"(d) : "l"(a), "l"(b));
}
__device__ __forceinline__ u64 fmul2(u64 a, u64 b) {
    u64 r; asm("mul.rn.f32x2 %0, %1, %2;" : "=l"(r) : "l"(a), "l"(b)); return r;
}
__device__ __forceinline__ u64 pack2(float x, float y) {
    u64 r; asm("mov.b64 %0, {%1, %2};" : "=l"(r) : "f"(x), "f"(y)); return r;
}
__device__ __forceinline__ float2 unpack2(u64 v) {
    float2 f; asm("mov.b64 {%0, %1}, %2;" : "=f"(f.x), "=f"(f.y) : "l"(v)); return f;
}
__device__ __forceinline__ float hadd2(u64 v) { float2 f = unpack2(v); return f.x + f.y; }
__device__ __forceinline__ float ex2(float x) {
    float r; asm("ex2.approx.f32 %0, %1;" : "=f"(r) : "f"(x)); return r;
}

__global__ void __launch_bounds__(THREADS, 2)
attn_kernel(const float* __restrict__ fc,   // [NPTS][C]
            const float* __restrict__ fn,   // [NPTS][KNB][C]
            float* __restrict__ out)        // [NPTS][C]
{
    // Per-warp tile: holds center features, later overwritten with y.
    __shared__ float sh[WARPS][PB*C];       // 32 KB / block

    const int warp = threadIdx.x >> 5;
    const int lane = threadIdx.x & 31;
    const int p0   = (blockIdx.x * WARPS + warp) * PB;
    float* xy = sh[warp];
    const int l4 = lane * 4;

    // ---- stage center features ----
#pragma unroll
    for (int p = 0; p < PB; ++p)
        *(float4*)(xy + p*C + l4) =
            *(const float4*)(fc + (size_t)(p0 + p)*C + l4);
    __syncwarp();

    // ---- Phase A: u[p][j] = sum_i B[i][j]*xc[p][i], packed over i-pairs ----
    u64 acc[PB][4];
#pragma unroll
    for (int p = 0; p < PB; ++p)
#pragma unroll
        for (int t = 0; t < 4; ++t) acc[p][t] = 0ULL;

#pragma unroll 1
    for (int I = 0; I < CH; I += 2) {
        ulonglong2 xv[PB];
#pragma unroll
        for (int p = 0; p < PB; ++p)
            xv[p] = *(const ulonglong2*)(xy + p*C + 2*I);   // pairs (I),(I+1)
#pragma unroll
        for (int s = 0; s < 2; ++s) {
            const ulonglong2* bp =
                (const ulonglong2*)(g_Bp + (size_t)((I + s)*C + l4)*2);
            const ulonglong2 b01 = bp[0];   // pairs for j0, j1
            const ulonglong2 b23 = bp[1];   // pairs for j2, j3
#pragma unroll
            for (int p = 0; p < PB; ++p) {
                const u64 xp = s ? xv[p].y : xv[p].x;
                ffma2(acc[p][0], b01.x, xp);
                ffma2(acc[p][1], b01.y, xp);
                ffma2(acc[p][2], b23.x, xp);
                ffma2(acc[p][3], b23.y, xp);
            }
        }
    }

    // Repack u as j-pairs for the middle dots (lane owns j = l4..l4+3).
    u64 up01[PB], up23[PB];
#pragma unroll
    for (int p = 0; p < PB; ++p) {
        up01[p] = pack2(hadd2(acc[p][0]), hadd2(acc[p][1]));
        up23[p] = pack2(hadd2(acc[p][2]), hadd2(acc[p][3]));
    }

    // ---- center logits, batched butterfly (ILP 8) ----
    float dc[PB];
#pragma unroll
    for (int p = 0; p < PB; ++p) {
        const ulonglong2 cv = *(const ulonglong2*)(xy + p*C + l4);
        u64 t = fmul2(up01[p], cv.x);
        ffma2(t, up23[p], cv.y);
        dc[p] = hadd2(t);
    }
#pragma unroll
    for (int off = 16; off; off >>= 1)
#pragma unroll
        for (int p = 0; p < PB; ++p)
            dc[p] += __shfl_xor_sync(0xffffffffu, dc[p], off);

    // ---- middle: online softmax, point-pairs for ILP ----
#pragma unroll 1
    for (int q = 0; q < PB; q += 2) {
        const float* xna = fn + (size_t)(p0 + q    )*(KNB*C);
        const float* xnb = fn + (size_t)(p0 + q + 1)*(KNB*C);
        const ulonglong2 ca = *(const ulonglong2*)(xy + q*C + l4);
        const ulonglong2 cb = *(const ulonglong2*)(xy + (q+1)*C + l4);
        float ma = dc[q], mb = dc[q+1];
        float sa = 1.f,  sb = 1.f;
        u64 ya0 = ca.x, ya1 = ca.y;      // y starts at center with weight 1
        u64 yb0 = cb.x, yb1 = cb.y;

#pragma unroll
        for (int ck = 0; ck < 4; ++ck) {
            ulonglong2 xa[4], xb[4];
#pragma unroll
            for (int nb = 0; nb < 4; ++nb)
                xa[nb] = *(const ulonglong2*)(xna + (ck*4 + nb)*C + l4);
#pragma unroll
            for (int nb = 0; nb < 4; ++nb)
                xb[nb] = *(const ulonglong2*)(xnb + (ck*4 + nb)*C + l4);

            float d[8];
#pragma unroll
            for (int nb = 0; nb < 4; ++nb) {
                u64 t = fmul2(up01[q], xa[nb].x);
                ffma2(t, up23[q], xa[nb].y);
                d[nb] = hadd2(t);
            }
#pragma unroll
            for (int nb = 0; nb < 4; ++nb) {
                u64 t = fmul2(up01[q+1], xb[nb].x);
                ffma2(t, up23[q+1], xb[nb].y);
                d[4+nb] = hadd2(t);
            }
#pragma unroll
            for (int off = 16; off; off >>= 1)
#pragma unroll
                for (int r = 0; r < 8; ++r)
                    d[r] += __shfl_xor_sync(0xffffffffu, d[r], off);

            // online update (log2 domain; scale folded into B)
            float mna = ma, mnb = mb;
#pragma unroll
            for (int nb = 0; nb < 4; ++nb) { mna = fmaxf(mna, d[nb]); mnb = fmaxf(mnb, d[4+nb]); }
            const float fa = ex2(ma - mna), fb = ex2(mb - mnb);
            sa *= fa; sb *= fb;
            const u64 fda = pack2(fa, fa), fdb = pack2(fb, fb);
            ya0 = fmul2(ya0, fda); ya1 = fmul2(ya1, fda);
            yb0 = fmul2(yb0, fdb); yb1 = fmul2(yb1, fdb);
#pragma unroll
            for (int nb = 0; nb < 4; ++nb) {
                const float wa = ex2(d[nb]   - mna);
                const float wb = ex2(d[4+nb] - mnb);
                sa += wa; sb += wb;
                const u64 wda = pack2(wa, wa), wdb = pack2(wb, wb);
                ffma2(ya0, wda, xa[nb].x);
                ffma2(ya1, wda, xa[nb].y);
                ffma2(yb0, wdb, xb[nb].x);
                ffma2(yb1, wdb, xb[nb].y);
            }
            ma = mna; mb = mnb;
        }
        const float ra = __fdividef(1.f, sa), rb = __fdividef(1.f, sb);
        const u64 rda = pack2(ra, ra), rdb = pack2(rb, rb);
        ulonglong2 wa2, wb2;
        wa2.x = fmul2(ya0, rda); wa2.y = fmul2(ya1, rda);
        wb2.x = fmul2(yb0, rdb); wb2.y = fmul2(yb1, rdb);
        *(ulonglong2*)(xy + q*C + l4)     = wa2;   // overwrite center slot with y
        *(ulonglong2*)(xy + (q+1)*C + l4) = wb2;
    }
    __syncwarp();

    // ---- Phase C: out[p][o] = sum_i wvT[i][o]*y[p][i], packed over i-pairs ----
    u64 oac[PB][4];
#pragma unroll
    for (int p = 0; p < PB; ++p)
#pragma unroll
        for (int t = 0; t < 4; ++t) oac[p][t] = 0ULL;

#pragma unroll 1
    for (int I = 0; I < CH; I += 2) {
        ulonglong2 yv[PB];
#pragma unroll
        for (int p = 0; p < PB; ++p)
            yv[p] = *(const ulonglong2*)(xy + p*C + 2*I);
#pragma unroll
        for (int s = 0; s < 2; ++s) {
            const ulonglong2* wp =
                (const ulonglong2*)(g_wvp + (size_t)((I + s)*C + l4)*2);
            const ulonglong2 w01 = wp[0];
            const ulonglong2 w23 = wp[1];
#pragma unroll
            for (int p = 0; p < PB; ++p) {
                const u64 yp = s ? yv[p].y : yv[p].x;
                ffma2(oac[p][0], w01.x, yp);
                ffma2(oac[p][1], w01.y, yp);
                ffma2(oac[p][2], w23.x, yp);
                ffma2(oac[p][3], w23.y, yp);
            }
        }
    }
#pragma unroll
    for (int p = 0; p < PB; ++p) {
        float4 o;
        o.x = hadd2(oac[p][0]);
        o.y = hadd2(oac[p][1]);
        o.z = hadd2(oac[p][2]);
        o.w = hadd2(oac[p][3]);
        *(float4*)(out + (size_t)(p0 + p)*C + l4) = o;
    }
}

extern "C" void kernel_launch(void* const* d_in, const int* in_sizes, int n_in,
                              void* d_out, int out_size) {
    const float* fc = (const float*)d_in[0];   // fea_center [8,4096,1,128]
    const float* fn = (const float*)d_in[1];   // fea_near   [8,4096,16,128]
    const float* wq = (const float*)d_in[2];   // [64,128]
    const float* wk = (const float*)d_in[3];   // [64,128]
    const float* wv = (const float*)d_in[4];   // [128,128]
    float* out = (float*)d_out;                // [8,4096,128]

    precompute_kernel<<<C, C>>>(wq, wk, wv);
    attn_kernel<<<NPTS/(PB*WARPS), THREADS>>>(fc, fn, out);
}

// round 4
// speedup vs baseline: 1.0059x; 1.0059x over previous
#include <cuda_runtime.h>
#include <cstdint>

#define C      128
#define CH     64
#define KNB    16
#define CHUNK  4                 // neighbor rows per pipeline stage
#define NST    4                 // ring depth (stages in flight)
#define PB     8                 // points per warp
#define WARPS  4
#define THREADS 128
#define NPTS   (8*4096)
#define NSTAGE_TOT (PB*4)        // 32 stages per warp-task

// Weight scratch (device globals; no allocation in kernel_launch)
__device__ float g_B[C*C];     // B[i][j] = sum_o wq[o][i]*wk[o][j] * 0.125*log2e
__device__ float g_wvT[C*C];   // wvT[i][o] = wv[o][i]

__global__ void precompute_kernel(const float* __restrict__ wq,
                                  const float* __restrict__ wk,
                                  const float* __restrict__ wv) {
    const int i = blockIdx.x;   // input channel
    const int j = threadIdx.x;  // output channel
    float acc = 0.f;
#pragma unroll
    for (int o = 0; o < CH; ++o)
        acc = fmaf(wq[o*C + i], wk[o*C + j], acc);
    g_B[i*C + j]   = acc * (0.125f * 1.4426950408889634f); // fold scale+log2e
    g_wvT[i*C + j] = wv[j*C + i];
}

__device__ __forceinline__ float ex2(float x) {
    float r; asm("ex2.approx.f32 %0, %1;" : "=f"(r) : "f"(x)); return r;
}
__device__ __forceinline__ float dot4(const float4 a, const float4 b) {
    float t = a.x * b.x;
    t = fmaf(a.y, b.y, t);
    t = fmaf(a.z, b.z, t);
    t = fmaf(a.w, b.w, t);
    return t;
}
__device__ __forceinline__ void cp16(uint32_t dst, const void* src) {
    asm volatile("cp.async.ca.shared.global [%0], [%1], 16;" :: "r"(dst), "l"(src));
}
__device__ __forceinline__ void cp_commit() {
    asm volatile("cp.async.commit_group;" ::: "memory");
}
__device__ __forceinline__ void cp_wait3() {
    asm volatile("cp.async.wait_group %0;" :: "n"(NST-1) : "memory");
}

__global__ void __launch_bounds__(THREADS, 4)
attn_kernel(const float* __restrict__ fc,   // [NPTS][C]
            const float* __restrict__ fn,   // [NPTS][KNB][C]
            float* __restrict__ out)        // [NPTS][C]
{
    __shared__ __align__(16) float s_xcy [WARPS][PB*C];          // 16 KB
    __shared__ __align__(16) float s_ring[WARPS][NST*CHUNK*C];   // 32 KB

    const int warp = threadIdx.x >> 5;
    const int lane = threadIdx.x & 31;
    const int p0   = (blockIdx.x * WARPS + warp) * PB;
    const int l4   = lane * 4;

    float* xy   = s_xcy[warp];
    float* ring = s_ring[warp];
    const uint32_t ring_base =
        (uint32_t)__cvta_generic_to_shared(ring) + (uint32_t)(l4 * 4);
    const float* fnw = fn + (size_t)p0 * (KNB*C);

    // ---- prologue: start the fn pipeline immediately (stages 0..NST-1) ----
#pragma unroll
    for (int s = 0; s < NST; ++s) {
        const int p = s >> 2, ck = s & 3;
        const float* src = fnw + ((size_t)p*KNB + ck*CHUNK)*C + l4;
        const uint32_t dst = ring_base + (uint32_t)((s & (NST-1)) * CHUNK*C * 4);
#pragma unroll
        for (int r = 0; r < CHUNK; ++r)
            cp16(dst + r*C*4, src + r*C);
        cp_commit();
    }

    // ---- stage center features into shared ----
#pragma unroll
    for (int p = 0; p < PB; ++p)
        *(float4*)(xy + p*C + l4) =
            *(const float4*)(fc + (size_t)(p0 + p)*C + l4);
    __syncwarp();

    // ---- Phase A: u[p][j] = sum_i B[i][j]*xc[p][i]  (lane owns j=l4..l4+3) ----
    float4 u4[PB];
#pragma unroll
    for (int p = 0; p < PB; ++p) u4[p] = make_float4(0.f, 0.f, 0.f, 0.f);
#pragma unroll 2
    for (int i0 = 0; i0 < C; i0 += 4) {
        float4 c4[PB];
#pragma unroll
        for (int p = 0; p < PB; ++p)
            c4[p] = *(const float4*)(xy + p*C + i0);     // smem broadcast
#pragma unroll
        for (int di = 0; di < 4; ++di) {
            const float4 b4 = *(const float4*)(g_B + (i0 + di)*C + l4);
#pragma unroll
            for (int p = 0; p < PB; ++p) {
                const float cv = (&c4[p].x)[di];
                u4[p].x = fmaf(b4.x, cv, u4[p].x);
                u4[p].y = fmaf(b4.y, cv, u4[p].y);
                u4[p].z = fmaf(b4.z, cv, u4[p].z);
                u4[p].w = fmaf(b4.w, cv, u4[p].w);
            }
        }
    }

    // ---- center logits for all PB points, batched butterfly ----
    float dc[PB];
#pragma unroll
    for (int p = 0; p < PB; ++p)
        dc[p] = dot4(u4[p], *(const float4*)(xy + p*C + l4));
#pragma unroll
    for (int off = 16; off; off >>= 1)
#pragma unroll
        for (int p = 0; p < PB; ++p)
            dc[p] += __shfl_xor_sync(0xffffffffu, dc[p], off);

    // ---- middle: online softmax over 16 neighbors + center, pipelined ----
#pragma unroll 1
    for (int p = 0; p < PB; ++p) {
        const float4 up = u4[p];
        const float4 c4 = *(const float4*)(xy + p*C + l4);
        float m = dc[p];           // log2-domain (scale folded into B)
        float ss = 1.f;            // running sum (center has weight 1)
        float4 y = c4;

#pragma unroll
        for (int ck = 0; ck < 4; ++ck) {
            const int s = p*4 + ck;
            cp_wait3();                       // stage s resident
            const float* rp = ring + (s & (NST-1))*CHUNK*C;
            float4 x0 = *(const float4*)(rp + 0*C + l4);
            float4 x1 = *(const float4*)(rp + 1*C + l4);
            float4 x2 = *(const float4*)(rp + 2*C + l4);
            float4 x3 = *(const float4*)(rp + 3*C + l4);

            // refill the slot we just freed (stage s+NST)
            if (s + NST < NSTAGE_TOT) {
                const int sn = s + NST, pn = sn >> 2, ckn = sn & 3;
                const float* src = fnw + ((size_t)pn*KNB + ckn*CHUNK)*C + l4;
                const uint32_t dst =
                    ring_base + (uint32_t)((sn & (NST-1)) * CHUNK*C * 4);
#pragma unroll
                for (int r = 0; r < CHUNK; ++r)
                    cp16(dst + r*C*4, src + r*C);
            }
            cp_commit();   // keep group count in lockstep even on tail

            float d0 = dot4(up, x0), d1 = dot4(up, x1);
            float d2 = dot4(up, x2), d3 = dot4(up, x3);
#pragma unroll
            for (int off = 16; off; off >>= 1) {
                d0 += __shfl_xor_sync(0xffffffffu, d0, off);
                d1 += __shfl_xor_sync(0xffffffffu, d1, off);
                d2 += __shfl_xor_sync(0xffffffffu, d2, off);
                d3 += __shfl_xor_sync(0xffffffffu, d3, off);
            }
            float mn = fmaxf(fmaxf(fmaxf(m, d0), fmaxf(d1, d2)), d3);
            const float f = ex2(m - mn);
            const float w0 = ex2(d0 - mn), w1 = ex2(d1 - mn);
            const float w2 = ex2(d2 - mn), w3 = ex2(d3 - mn);
            ss = fmaf(ss, f, w0 + w1 + w2 + w3);
            y.x = y.x*f; y.y = y.y*f; y.z = y.z*f; y.w = y.w*f;
            y.x = fmaf(w0, x0.x, y.x); y.y = fmaf(w0, x0.y, y.y);
            y.z = fmaf(w0, x0.z, y.z); y.w = fmaf(w0, x0.w, y.w);
            y.x = fmaf(w1, x1.x, y.x); y.y = fmaf(w1, x1.y, y.y);
            y.z = fmaf(w1, x1.z, y.z); y.w = fmaf(w1, x1.w, y.w);
            y.x = fmaf(w2, x2.x, y.x); y.y = fmaf(w2, x2.y, y.y);
            y.z = fmaf(w2, x2.z, y.z); y.w = fmaf(w2, x2.w, y.w);
            y.x = fmaf(w3, x3.x, y.x); y.y = fmaf(w3, x3.y, y.y);
            y.z = fmaf(w3, x3.z, y.z); y.w = fmaf(w3, x3.w, y.w);
            m = mn;
        }
        const float rs = __fdividef(1.f, ss);
        y.x *= rs; y.y *= rs; y.z *= rs; y.w *= rs;
        *(float4*)(xy + p*C + l4) = y;   // overwrite center slot with y
    }
    __syncwarp();

    // ---- Phase C: out[p][o] = sum_i wvT[i][o]*y[p][i] ----
    float4 o4[PB];
#pragma unroll
    for (int p = 0; p < PB; ++p) o4[p] = make_float4(0.f, 0.f, 0.f, 0.f);
#pragma unroll 2
    for (int i0 = 0; i0 < C; i0 += 4) {
        float4 y4[PB];
#pragma unroll
        for (int p = 0; p < PB; ++p)
            y4[p] = *(const float4*)(xy + p*C + i0);     // smem broadcast
#pragma unroll
        for (int di = 0; di < 4; ++di) {
            const float4 w4 = *(const float4*)(g_wvT + (i0 + di)*C + l4);
#pragma unroll
            for (int p = 0; p < PB; ++p) {
                const float yv = (&y4[p].x)[di];
                o4[p].x = fmaf(w4.x, yv, o4[p].x);
                o4[p].y = fmaf(w4.y, yv, o4[p].y);
                o4[p].z = fmaf(w4.z, yv, o4[p].z);
                o4[p].w = fmaf(w4.w, yv, o4[p].w);
            }
        }
    }
#pragma unroll
    for (int p = 0; p < PB; ++p)
        *(float4*)(out + (size_t)(p0 + p)*C + l4) = o4[p];
}

extern "C" void kernel_launch(void* const* d_in, const int* in_sizes, int n_in,
                              void* d_out, int out_size) {
    const float* fc = (const float*)d_in[0];   // fea_center [8,4096,1,128]
    const float* fn = (const float*)d_in[1];   // fea_near   [8,4096,16,128]
    const float* wq = (const float*)d_in[2];   // [64,128]
    const float* wk = (const float*)d_in[3];   // [64,128]
    const float* wv = (const float*)d_in[4];   // [128,128]
    float* out = (float*)d_out;                // [8,4096,128]

    precompute_kernel<<<C, C>>>(wq, wk, wv);
    attn_kernel<<<NPTS/(PB*WARPS), THREADS>>>(fc, fn, out);
}